// round 15
// baseline (speedup 1.0000x reference)
#include <cuda_runtime.h>
#include <cuda_bf16.h>
#include <math.h>

#define BB    64
#define POMO  200
#define PROB  200
#define NNODE 201
#define EMB   512
#define NH    16
#define HD    32

// ---------------------------------------------------------------------------
// Scratch
// ---------------------------------------------------------------------------
__device__ __nv_bfloat16 g_nh [BB * NNODE * EMB], g_nl [BB * NNODE * EMB];
__device__ __nv_bfloat16 g_q1h[BB * POMO  * EMB], g_q1l[BB * POMO  * EMB];
__device__ __nv_bfloat16 g_lnh[BB * POMO  * EMB], g_lnl[BB * POMO  * EMB];
__device__ __nv_bfloat16 g_Kh [BB * NNODE * EMB], g_Kl [BB * NNODE * EMB];
__device__ __nv_bfloat16 g_Vh [BB * NNODE * EMB], g_Vl [BB * NNODE * EMB];
__device__ __nv_bfloat16 g_Qh [BB * POMO  * EMB], g_Ql [BB * POMO  * EMB];
__device__ __nv_bfloat16 g_Oh [BB * POMO  * EMB], g_Ol [BB * POMO  * EMB];
__device__ __nv_bfloat16 g_MHh[BB * POMO  * EMB], g_MHl[BB * POMO  * EMB];
__device__ __nv_bfloat16 g_Wkh [EMB * EMB], g_Wkl [EMB * EMB];
__device__ __nv_bfloat16 g_Wvh [EMB * EMB], g_Wvl [EMB * EMB];
__device__ __nv_bfloat16 g_Wqfh[EMB * EMB], g_Wqfl[EMB * EMB];
__device__ __nv_bfloat16 g_Wqlh[EMB * EMB], g_Wqll[EMB * EMB];
__device__ __nv_bfloat16 g_Wch [EMB * EMB], g_Wcl [EMB * EMB];

// ---------------------------------------------------------------------------
// Helpers
// ---------------------------------------------------------------------------
__device__ __forceinline__ unsigned smem_u32(const void* p) {
    return (unsigned)__cvta_generic_to_shared(p);
}
__device__ __forceinline__ void cp16(unsigned d, const void* s) {
    asm volatile("cp.async.cg.shared.global [%0], [%1], 16;" :: "r"(d), "l"(s));
}
#define CP_COMMIT() asm volatile("cp.async.commit_group;")
#define CP_WAIT1()  asm volatile("cp.async.wait_group 1;")
#define CP_WAIT0()  asm volatile("cp.async.wait_group 0;")

__device__ __forceinline__ void mma_bf16(float* c, const unsigned* a, const unsigned* b) {
    asm volatile(
        "mma.sync.aligned.m16n8k16.row.col.f32.bf16.bf16.f32 "
        "{%0,%1,%2,%3}, {%4,%5,%6,%7}, {%8,%9}, {%0,%1,%2,%3};\n"
        : "+f"(c[0]), "+f"(c[1]), "+f"(c[2]), "+f"(c[3])
        : "r"(a[0]), "r"(a[1]), "r"(a[2]), "r"(a[3]), "r"(b[0]), "r"(b[1]));
}

__device__ __forceinline__ void ldsm_x4(unsigned* r, unsigned addr) {
    asm volatile("ldmatrix.sync.aligned.m8n8.x4.shared.b16 {%0,%1,%2,%3}, [%4];"
        : "=r"(r[0]), "=r"(r[1]), "=r"(r[2]), "=r"(r[3]) : "r"(addr));
}

__device__ __forceinline__ void split2(float x, __nv_bfloat16& h, __nv_bfloat16& l) {
    h = __float2bfloat16_rn(x);
    l = __float2bfloat16_rn(x - __bfloat162float(h));
}

__device__ __forceinline__ void pks(float x, float y, unsigned& hi, unsigned& lo) {
    __nv_bfloat16 hx = __float2bfloat16_rn(x), hy = __float2bfloat16_rn(y);
    __nv_bfloat16 lx = __float2bfloat16_rn(x - __bfloat162float(hx));
    __nv_bfloat16 ly = __float2bfloat16_rn(y - __bfloat162float(hy));
    __nv_bfloat162 th(hx, hy), tl(lx, ly);
    hi = *reinterpret_cast<unsigned*>(&th);
    lo = *reinterpret_cast<unsigned*>(&tl);
}

// ldmatrix per-thread address offset (u32 units) within a 16x16 tile whose
// rows have pitch KP u32: lanes 0-7 -> m0(rows 0-7, k0-7), 8-15 -> m1(+8 rows),
// 16-23 -> m2(+16B k), 24-31 -> m3(both).
#define KP  12
__device__ __forceinline__ unsigned ldsm_off_u32(int lane) {
    return (unsigned)(((lane & 7) + ((lane >> 3) & 1) * 8) * KP + ((lane >> 4) & 1) * 4);
}

// ---------------------------------------------------------------------------
// convsplit3: three fp32 arrays -> bf16 hi/lo, z-indexed
// ---------------------------------------------------------------------------
__global__ __launch_bounds__(256) void convsplit3(
    const float* __restrict__ X0, __nv_bfloat16* __restrict__ H0, __nv_bfloat16* __restrict__ L0, int n0,
    const float* __restrict__ X1, __nv_bfloat16* __restrict__ H1, __nv_bfloat16* __restrict__ L1, int n1,
    const float* __restrict__ X2, __nv_bfloat16* __restrict__ H2, __nv_bfloat16* __restrict__ L2, int n2)
{
    const float* X; __nv_bfloat16 *H, *L; int n;
    if (blockIdx.z == 0)      { X = X0; H = H0; L = L0; n = n0; }
    else if (blockIdx.z == 1) { X = X1; H = H1; L = L1; n = n1; }
    else                      { X = X2; H = H2; L = L2; n = n2; }
    int i = (blockIdx.x * 256 + threadIdx.x) * 4;
    if (i >= n) return;
    float4 v = *(const float4*)(X + i);
    __nv_bfloat16 h0, l0, h1, l1, h2, l2, h3, l3;
    split2(v.x, h0, l0); split2(v.y, h1, l1);
    split2(v.z, h2, l2); split2(v.w, h3, l3);
    *(__nv_bfloat162*)(H + i)     = __nv_bfloat162(h0, h1);
    *(__nv_bfloat162*)(H + i + 2) = __nv_bfloat162(h2, h3);
    *(__nv_bfloat162*)(L + i)     = __nv_bfloat162(l0, l1);
    *(__nv_bfloat162*)(L + i + 2) = __nv_bfloat162(l2, l3);
}

// ---------------------------------------------------------------------------
// transconv5: 5 weight transposes+splits in one launch, z-indexed
// ---------------------------------------------------------------------------
__global__ __launch_bounds__(256) void transconv5(
    const float* W0, __nv_bfloat16* Th0, __nv_bfloat16* Tl0,
    const float* W1, __nv_bfloat16* Th1, __nv_bfloat16* Tl1,
    const float* W2, __nv_bfloat16* Th2, __nv_bfloat16* Tl2,
    const float* W3, __nv_bfloat16* Th3, __nv_bfloat16* Tl3,
    const float* W4, __nv_bfloat16* Th4, __nv_bfloat16* Tl4)
{
    const float* W; __nv_bfloat16 *Th, *Tl;
    switch (blockIdx.z) {
        case 0: W = W0; Th = Th0; Tl = Tl0; break;
        case 1: W = W1; Th = Th1; Tl = Tl1; break;
        case 2: W = W2; Th = Th2; Tl = Tl2; break;
        case 3: W = W3; Th = Th3; Tl = Tl3; break;
        default: W = W4; Th = Th4; Tl = Tl4; break;
    }
    __shared__ float t[32][33];
    const int tx = threadIdx.x, ty = threadIdx.y;   // (32, 8)
    const int x = blockIdx.x * 32 + tx;
    const int y = blockIdx.y * 32;
#pragma unroll
    for (int i = 0; i < 32; i += 8)
        t[ty + i][tx] = W[(size_t)(y + ty + i) * EMB + x];
    __syncthreads();
    const int xo = blockIdx.y * 32 + tx;
    const int yo = blockIdx.x * 32;
#pragma unroll
    for (int i = 0; i < 32; i += 8) {
        float v = t[tx][ty + i];
        __nv_bfloat16 h, l;
        split2(v, h, l);
        size_t o = (size_t)(yo + ty + i) * EMB + xo;
        Th[o] = h; Tl[o] = l;
    }
}

// ---------------------------------------------------------------------------
// bf16x3 GEMM body (128x128 tile, BK=16, 3-stage cp.async, ldmatrix frags)
// ---------------------------------------------------------------------------
#define GST 3
#define ATI (128 * KP)

__device__ __forceinline__ void gemm_body(
    const __nv_bfloat16* __restrict__ Ah,  const __nv_bfloat16* __restrict__ Al,
    const __nv_bfloat16* __restrict__ Bh,  const __nv_bfloat16* __restrict__ Bl,
    const __nv_bfloat16* __restrict__ A2h, const __nv_bfloat16* __restrict__ A2l,
    const __nv_bfloat16* __restrict__ B2h, const __nv_bfloat16* __restrict__ B2l,
    const float* __restrict__ bias, float* __restrict__ C,
    __nv_bfloat16* __restrict__ Ch, __nv_bfloat16* __restrict__ Cl,
    int M, int N, int K, int bm, int bn, unsigned* smu)
{
    unsigned* sAh = smu;
    unsigned* sAl = smu + GST * ATI;
    unsigned* sBh = smu + 2 * GST * ATI;
    unsigned* sBl = smu + 3 * GST * ATI;

    const int tid  = threadIdx.x;
    const int lane = tid & 31, warp = tid >> 5;
    const int g    = lane >> 2, tig = lane & 3;
    const int wm   = warp >> 2, wn  = warp & 3;

    const int SK = K / 16;
    const int S  = A2h ? 2 * SK : SK;

    const int r    = tid >> 1;
    const int half = tid & 1;

    auto load_tile = [&](int st, int t) {
        const __nv_bfloat16 *pAh, *pAl, *pBh, *pBl; int k0;
        if (t >= SK) { pAh = A2h; pAl = A2l; pBh = B2h; pBl = B2l; k0 = (t - SK) << 4; }
        else         { pAh = Ah;  pAl = Al;  pBh = Bh;  pBl = Bl;  k0 = t << 4; }
        int gr = bm + r; if (gr >= M) gr = M - 1;
        const int gn = bn + r;
        const unsigned off = st * ATI + r * KP + half * 4;
        const size_t ga = (size_t)gr * K + k0 + half * 8;
        const size_t gb = (size_t)gn * K + k0 + half * 8;
        cp16(smem_u32(sAh + off), pAh + ga);
        cp16(smem_u32(sAl + off), pAl + ga);
        cp16(smem_u32(sBh + off), pBh + gb);
        cp16(smem_u32(sBl + off), pBl + gb);
    };

    float acc[4][4][4];
#pragma unroll
    for (int i = 0; i < 4; ++i)
#pragma unroll
        for (int j = 0; j < 4; ++j)
#pragma unroll
            for (int t = 0; t < 4; ++t) acc[i][j][t] = 0.f;

#pragma unroll
    for (int t = 0; t < GST - 1; ++t) {
        if (t < S) load_tile(t, t);
        CP_COMMIT();
    }

    const unsigned uAh = smem_u32(sAh), uAl = smem_u32(sAl);
    const unsigned uBh = smem_u32(sBh), uBl = smem_u32(sBl);
    const unsigned aoffB = ldsm_off_u32(lane) * 4;

    for (int s = 0; s < S; ++s) {
        CP_WAIT1();
        __syncthreads();
        const int nt = s + GST - 1;
        if (nt < S) load_tile(nt % GST, nt);
        CP_COMMIT();

        const unsigned stB = (unsigned)((s % GST) * ATI) * 4;

        unsigned ah[4][4], al[4][4], bh[4][2], bl[4][2];
#pragma unroll
        for (int mf = 0; mf < 4; ++mf) {
            const unsigned rb = stB + (unsigned)((wm * 64 + mf * 16) * KP) * 4 + aoffB;
            ldsm_x4(ah[mf], uAh + rb);
            ldsm_x4(al[mf], uAl + rb);
        }
#pragma unroll
        for (int np = 0; np < 2; ++np) {
            const unsigned rb = stB + (unsigned)((wn * 32 + np * 16) * KP) * 4 + aoffB;
            unsigned rh[4], rl[4];
            ldsm_x4(rh, uBh + rb);
            ldsm_x4(rl, uBl + rb);
            bh[np * 2][0] = rh[0]; bh[np * 2 + 1][0] = rh[1];
            bh[np * 2][1] = rh[2]; bh[np * 2 + 1][1] = rh[3];
            bl[np * 2][0] = rl[0]; bl[np * 2 + 1][0] = rl[1];
            bl[np * 2][1] = rl[2]; bl[np * 2 + 1][1] = rl[3];
        }
#pragma unroll
        for (int mf = 0; mf < 4; ++mf)
#pragma unroll
            for (int nf = 0; nf < 4; ++nf)
                mma_bf16(acc[mf][nf], ah[mf], bh[nf]);
#pragma unroll
        for (int mf = 0; mf < 4; ++mf)
#pragma unroll
            for (int nf = 0; nf < 4; ++nf)
                mma_bf16(acc[mf][nf], al[mf], bh[nf]);
#pragma unroll
        for (int mf = 0; mf < 4; ++mf)
#pragma unroll
            for (int nf = 0; nf < 4; ++nf)
                mma_bf16(acc[mf][nf], ah[mf], bl[nf]);
    }

#pragma unroll
    for (int nf = 0; nf < 4; ++nf) {
        const int c0 = bn + wn * 32 + nf * 8 + 2 * tig;
        float bb0 = 0.f, bb1 = 0.f;
        if (bias) { bb0 = bias[c0]; bb1 = bias[c0 + 1]; }
#pragma unroll
        for (int mf = 0; mf < 4; ++mf) {
#pragma unroll
            for (int half8 = 0; half8 < 2; ++half8) {
                const int r0 = bm + wm * 64 + mf * 16 + g + half8 * 8;
                if (r0 >= M) continue;
                const float v0 = acc[mf][nf][2 * half8 + 0] + bb0;
                const float v1 = acc[mf][nf][2 * half8 + 1] + bb1;
                if (C) {
                    float2 v; v.x = v0; v.y = v1;
                    *(float2*)(C + (size_t)r0 * N + c0) = v;
                }
                if (Ch) {
                    __nv_bfloat16 h0, l0, h1, l1;
                    split2(v0, h0, l0); split2(v1, h1, l1);
                    *(__nv_bfloat162*)(Ch + (size_t)r0 * N + c0) = __nv_bfloat162(h0, h1);
                    *(__nv_bfloat162*)(Cl + (size_t)r0 * N + c0) = __nv_bfloat162(l0, l1);
                }
            }
        }
    }
}

__global__ __launch_bounds__(256, 1) void gemm_bf16x3(
    const __nv_bfloat16* __restrict__ Ah,  const __nv_bfloat16* __restrict__ Al,
    const __nv_bfloat16* __restrict__ Bh,  const __nv_bfloat16* __restrict__ Bl,
    const __nv_bfloat16* __restrict__ A2h, const __nv_bfloat16* __restrict__ A2l,
    const __nv_bfloat16* __restrict__ B2h, const __nv_bfloat16* __restrict__ B2l,
    const float* __restrict__ bias, float* __restrict__ C,
    __nv_bfloat16* __restrict__ Ch, __nv_bfloat16* __restrict__ Cl,
    int M, int N, int K)
{
    extern __shared__ unsigned smu[];
    gemm_body(Ah, Al, Bh, Bl, A2h, A2l, B2h, B2l, bias, C, Ch, Cl,
              M, N, K, blockIdx.y * 128, blockIdx.x * 128, smu);
}

// Fused K+V projection: grid.x spans 1024 output cols; CTA picks half.
__global__ __launch_bounds__(256, 1) void gemm_kv(
    const __nv_bfloat16* __restrict__ nh, const __nv_bfloat16* __restrict__ nl,
    const __nv_bfloat16* __restrict__ Wkh, const __nv_bfloat16* __restrict__ Wkl,
    const __nv_bfloat16* __restrict__ Wvh, const __nv_bfloat16* __restrict__ Wvl,
    __nv_bfloat16* __restrict__ Kh, __nv_bfloat16* __restrict__ Kl,
    __nv_bfloat16* __restrict__ Vh, __nv_bfloat16* __restrict__ Vl, int M)
{
    extern __shared__ unsigned smu[];
    int bn = blockIdx.x * 128;
    const __nv_bfloat16 *Bh, *Bl; __nv_bfloat16 *Ch, *Cl;
    if (bn < EMB) { Bh = Wkh; Bl = Wkl; Ch = Kh; Cl = Kl; }
    else          { bn -= EMB; Bh = Wvh; Bl = Wvl; Ch = Vh; Cl = Vl; }
    gemm_body(nh, nl, Bh, Bl, nullptr, nullptr, nullptr, nullptr,
              nullptr, nullptr, Ch, Cl, M, EMB, EMB, blockIdx.y * 128, bn, smu);
}

// ---------------------------------------------------------------------------
// Tensor-core flash attention (unchanged from passing round 10)
// ---------------------------------------------------------------------------
#define AT_KP 20
#define AT_VP 108
#define AT_MP 204
#define ATTN_SMEM (2*208*AT_KP*4 + 2*32*AT_VP*4 + 64*AT_MP*4)  // 113152

__global__ __launch_bounds__(128, 2) void attn_mma(
    const __nv_bfloat16* __restrict__ Qh, const __nv_bfloat16* __restrict__ Ql,
    const __nv_bfloat16* __restrict__ Kh, const __nv_bfloat16* __restrict__ Kl,
    const __nv_bfloat16* __restrict__ Vh, const __nv_bfloat16* __restrict__ Vl,
    const float* __restrict__ mask,
    __nv_bfloat16* __restrict__ Oh, __nv_bfloat16* __restrict__ Ol)
{
    extern __shared__ char smc[];
    unsigned* sKh = (unsigned*)smc;
    unsigned* sKl = sKh + 208 * AT_KP;
    unsigned* sVh = sKl + 208 * AT_KP;
    unsigned* sVl = sVh + 32 * AT_VP;
    float*    sMk = (float*)(sVl + 32 * AT_VP);

    const int tid = threadIdx.x;
    const int bx = blockIdx.x, h = blockIdx.y, b = blockIdx.z;
    const int lane = tid & 31, w = tid >> 5;
    const int g = lane >> 2, tig = lane & 3;
    const int qbase = bx * 64;

    const unsigned* Khu = (const unsigned*)Kh;
    const unsigned* Klu = (const unsigned*)Kl;

    for (int i = tid; i < 201 * 4; i += 128) {
        const int row = i >> 2, c = i & 3;
        const size_t src = (((size_t)(b * NNODE + row) * EMB + h * HD) >> 1) + c * 4;
        const unsigned dst = row * AT_KP + c * 4;
        cp16(smem_u32(sKh + dst), Khu + src);
        cp16(smem_u32(sKl + dst), Klu + src);
    }
    for (int i = tid; i < 3200; i += 128) {
        const int r = i / 50, c4 = i % 50;
        int grow = qbase + r; if (grow >= POMO) grow = POMO - 1;
        cp16(smem_u32(sMk + r * AT_MP + c4 * 4),
             mask + (size_t)(b * POMO + grow) * PROB + c4 * 4);
    }
    CP_COMMIT();

    {
        const __nv_bfloat162* Vh2 = (const __nv_bfloat162*)Vh;
        const __nv_bfloat162* Vl2 = (const __nv_bfloat162*)Vl;
        __nv_bfloat16* pVh = (__nv_bfloat16*)sVh;
        __nv_bfloat16* pVl = (__nv_bfloat16*)sVl;
        for (int i = tid; i < 201 * 16; i += 128) {
            const int row = i >> 4, wd = i & 15;
            const size_t src = (((size_t)(b * NNODE + row) * EMB + h * HD) >> 1) + wd;
            __nv_bfloat162 th = Vh2[src];
            __nv_bfloat162 tl = Vl2[src];
            const int d0 = wd * 2;
            pVh[d0 * 216 + row] = th.x; pVh[(d0 + 1) * 216 + row] = th.y;
            pVl[d0 * 216 + row] = tl.x; pVl[(d0 + 1) * 216 + row] = tl.y;
        }
        for (int i = tid; i < 7 * AT_KP; i += 128) {
            sKh[201 * AT_KP + i] = 0;
            sKl[201 * AT_KP + i] = 0;
        }
        const __nv_bfloat16 z = __float2bfloat16(0.f);
        for (int i = tid; i < 32 * 7; i += 128) {
            const int d = i / 7, c = 201 + i % 7;
            pVh[d * 216 + c] = z;
            pVl[d * 216 + c] = z;
        }
    }
    CP_WAIT0();
    __syncthreads();

    const int mt = bx * 4 + w;
    if (mt >= 13) return;

    const int qr0 = mt * 16 + g, qr1 = qr0 + 8;
    const int gr0 = b * POMO + (qr0 < POMO ? qr0 : POMO - 1);
    const int gr1 = b * POMO + (qr1 < POMO ? qr1 : POMO - 1);
    const unsigned* Qhu = (const unsigned*)Qh;
    const unsigned* Qlu = (const unsigned*)Ql;
    unsigned aQh[2][4], aQl[2][4];
#pragma unroll
    for (int ks = 0; ks < 2; ++ks) {
        const size_t s0 = (((size_t)gr0 * EMB + h * HD + ks * 16) >> 1) + tig;
        const size_t s1 = (((size_t)gr1 * EMB + h * HD + ks * 16) >> 1) + tig;
        aQh[ks][0] = Qhu[s0]; aQh[ks][1] = Qhu[s1];
        aQh[ks][2] = Qhu[s0 + 4]; aQh[ks][3] = Qhu[s1 + 4];
        aQl[ks][0] = Qlu[s0]; aQl[ks][1] = Qlu[s1];
        aQl[ks][2] = Qlu[s0 + 4]; aQl[ks][3] = Qlu[s1 + 4];
    }

    float Oacc[4][4];
#pragma unroll
    for (int i = 0; i < 4; ++i)
#pragma unroll
        for (int j = 0; j < 4; ++j) Oacc[i][j] = 0.f;
    float mx0 = -1e30f, mx1 = -1e30f, l0 = 0.f, l1 = 0.f;
    const float scale = 0.17677669529663687f;
    const int lr = w * 16 + g;

#pragma unroll 1
    for (int kt = 0; kt < 13; ++kt) {
        float c0[4] = {0.f, 0.f, 0.f, 0.f}, c1[4] = {0.f, 0.f, 0.f, 0.f};
#pragma unroll
        for (int nt = 0; nt < 2; ++nt) {
            float* cc = nt ? c1 : c0;
            const int key = kt * 16 + nt * 8 + g;
#pragma unroll
            for (int ks = 0; ks < 2; ++ks) {
                const unsigned base = key * AT_KP + ks * 8 + tig;
                unsigned bh[2] = { sKh[base], sKh[base + 4] };
                unsigned bl[2] = { sKl[base], sKl[base + 4] };
                mma_bf16(cc, aQh[ks], bh);
                mma_bf16(cc, aQl[ks], bh);
                mma_bf16(cc, aQh[ks], bl);
            }
        }
        float sv0[4], sv1[4];
        const int kbase = kt * 16 + 2 * tig;
#pragma unroll
        for (int j = 0; j < 4; ++j) {
            const int key = kbase + (j >> 1) * 8 + (j & 1);
            float mk0, mk1;
            if (key < PROB)      { mk0 = sMk[lr * AT_MP + key]; mk1 = sMk[(lr + 8) * AT_MP + key]; }
            else if (key == PROB){ mk0 = 0.f; mk1 = 0.f; }
            else                 { mk0 = -1e30f; mk1 = -1e30f; }
            const float* cc = (j < 2) ? c0 : c1;
            sv0[j] = fmaf(cc[j & 1], scale, mk0);
            sv1[j] = fmaf(cc[2 + (j & 1)], scale, mk1);
        }
        float m0 = fmaxf(fmaxf(sv0[0], sv0[1]), fmaxf(sv0[2], sv0[3]));
        float m1 = fmaxf(fmaxf(sv1[0], sv1[1]), fmaxf(sv1[2], sv1[3]));
        m0 = fmaxf(m0, __shfl_xor_sync(0xffffffffu, m0, 1));
        m0 = fmaxf(m0, __shfl_xor_sync(0xffffffffu, m0, 2));
        m1 = fmaxf(m1, __shfl_xor_sync(0xffffffffu, m1, 1));
        m1 = fmaxf(m1, __shfl_xor_sync(0xffffffffu, m1, 2));
        if (m0 > mx0) {
            const float a = __expf(mx0 - m0); mx0 = m0; l0 *= a;
#pragma unroll
            for (int vd = 0; vd < 4; ++vd) { Oacc[vd][0] *= a; Oacc[vd][1] *= a; }
        }
        if (m1 > mx1) {
            const float a = __expf(mx1 - m1); mx1 = m1; l1 *= a;
#pragma unroll
            for (int vd = 0; vd < 4; ++vd) { Oacc[vd][2] *= a; Oacc[vd][3] *= a; }
        }
        float p0[4], p1[4];
#pragma unroll
        for (int j = 0; j < 4; ++j) {
            p0[j] = __expf(sv0[j] - mx0);
            p1[j] = __expf(sv1[j] - mx1);
        }
        l0 += p0[0] + p0[1] + p0[2] + p0[3];
        l1 += p1[0] + p1[1] + p1[2] + p1[3];
        unsigned aPh[4], aPl[4];
        pks(p0[0], p0[1], aPh[0], aPl[0]);
        pks(p1[0], p1[1], aPh[1], aPl[1]);
        pks(p0[2], p0[3], aPh[2], aPl[2]);
        pks(p1[2], p1[3], aPh[3], aPl[3]);
#pragma unroll
        for (int vd = 0; vd < 4; ++vd) {
            const unsigned base = (vd * 8 + g) * AT_VP + kt * 8 + tig;
            unsigned bh[2] = { sVh[base], sVh[base + 4] };
            unsigned bl[2] = { sVl[base], sVl[base + 4] };
            mma_bf16(Oacc[vd], aPh, bh);
            mma_bf16(Oacc[vd], aPl, bh);
            mma_bf16(Oacc[vd], aPh, bl);
        }
    }

    l0 += __shfl_xor_sync(0xffffffffu, l0, 1);
    l0 += __shfl_xor_sync(0xffffffffu, l0, 2);
    l1 += __shfl_xor_sync(0xffffffffu, l1, 1);
    l1 += __shfl_xor_sync(0xffffffffu, l1, 2);

    const float i0 = 1.f / l0, i1 = 1.f / l1;
#pragma unroll
    for (int vd = 0; vd < 4; ++vd) {
        const int col = h * HD + vd * 8 + 2 * tig;
        if (qr0 < POMO) {
            const size_t o = (size_t)(b * POMO + qr0) * EMB + col;
            const float v0 = Oacc[vd][0] * i0, v1 = Oacc[vd][1] * i0;
            __nv_bfloat16 h0, lo0, h1, lo1;
            split2(v0, h0, lo0); split2(v1, h1, lo1);
            *(__nv_bfloat162*)(Oh + o) = __nv_bfloat162(h0, h1);
            *(__nv_bfloat162*)(Ol + o) = __nv_bfloat162(lo0, lo1);
        }
        if (qr1 < POMO) {
            const size_t o = (size_t)(b * POMO + qr1) * EMB + col;
            const float v0 = Oacc[vd][2] * i1, v1 = Oacc[vd][3] * i1;
            __nv_bfloat16 h0, lo0, h1, lo1;
            split2(v0, h0, lo0); split2(v1, h1, lo1);
            *(__nv_bfloat162*)(Oh + o) = __nv_bfloat162(h0, h1);
            *(__nv_bfloat162*)(Ol + o) = __nv_bfloat162(lo0, lo1);
        }
    }
}

// ---------------------------------------------------------------------------
// score2 bf16x3 with ldmatrix fragments (BM=64, BN=128)
// ---------------------------------------------------------------------------
#define S_ATI (64 * KP)
#define S_BTI (128 * KP)

__global__ __launch_bounds__(256, 2) void score2_bf16(
    const __nv_bfloat16* __restrict__ MHh, const __nv_bfloat16* __restrict__ MHl,
    const __nv_bfloat16* __restrict__ Nh,  const __nv_bfloat16* __restrict__ Nl,
    const float* __restrict__ mask, float* __restrict__ out)
{
    extern __shared__ unsigned smu[];
    unsigned* sAh = smu;
    unsigned* sAl = smu + GST * S_ATI;
    unsigned* sBh = smu + 2 * GST * S_ATI;
    unsigned* sBl = smu + 2 * GST * S_ATI + GST * S_BTI;

    const int tid  = threadIdx.x;
    const int lane = tid & 31, warp = tid >> 5;
    const int g    = lane >> 2, tig = lane & 3;
    const int wm   = warp >> 2, wn  = warp & 3;
    const int b    = blockIdx.z;
    const int bm   = blockIdx.y * 64, bn = blockIdx.x * 128;

    const int rb = tid >> 1, half = tid & 1;
    const int ra = (tid & 127) >> 1;

    auto load_tile = [&](int st, int t) {
        const int k0 = t << 4;
        int gb = bn + rb; if (gb >= PROB) gb = PROB - 1;
        const size_t go = ((size_t)b * NNODE + gb) * EMB + k0 + half * 8;
        const unsigned ob = st * S_BTI + rb * KP + half * 4;
        cp16(smem_u32(sBh + ob), Nh + go);
        cp16(smem_u32(sBl + ob), Nl + go);
        if (tid < 128) {
            int ga = bm + ra; if (ga >= POMO) ga = POMO - 1;
            const size_t ao = ((size_t)b * POMO + ga) * EMB + k0 + half * 8;
            const unsigned oa = st * S_ATI + ra * KP + half * 4;
            cp16(smem_u32(sAh + oa), MHh + ao);
            cp16(smem_u32(sAl + oa), MHl + ao);
        }
    };

    float acc[2][4][4];
#pragma unroll
    for (int i = 0; i < 2; ++i)
#pragma unroll
        for (int j = 0; j < 4; ++j)
#pragma unroll
            for (int t = 0; t < 4; ++t) acc[i][j][t] = 0.f;

    const int S = EMB / 16;
#pragma unroll
    for (int t = 0; t < GST - 1; ++t) {
        if (t < S) load_tile(t, t);
        CP_COMMIT();
    }

    const unsigned uAh = smem_u32(sAh), uAl = smem_u32(sAl);
    const unsigned uBh = smem_u32(sBh), uBl = smem_u32(sBl);
    const unsigned aoffB = ldsm_off_u32(lane) * 4;

    for (int s = 0; s < S; ++s) {
        CP_WAIT1();
        __syncthreads();
        const int nt = s + GST - 1;
        if (nt < S) load_tile(nt % GST, nt);
        CP_COMMIT();

        const unsigned stA = (unsigned)((s % GST) * S_ATI) * 4;
        const unsigned stBt = (unsigned)((s % GST) * S_BTI) * 4;

        unsigned ah[2][4], al[2][4], bh[4][2], bl[4][2];
#pragma unroll
        for (int mf = 0; mf < 2; ++mf) {
            const unsigned rbad = stA + (unsigned)((wm * 32 + mf * 16) * KP) * 4 + aoffB;
            ldsm_x4(ah[mf], uAh + rbad);
            ldsm_x4(al[mf], uAl + rbad);
        }
#pragma unroll
        for (int np = 0; np < 2; ++np) {
            const unsigned rbad = stBt + (unsigned)((wn * 32 + np * 16) * KP) * 4 + aoffB;
            unsigned rh[4], rl[4];
            ldsm_x4(rh, uBh + rbad);
            ldsm_x4(rl, uBl + rbad);
            bh[np * 2][0] = rh[0]; bh[np * 2 + 1][0] = rh[1];
            bh[np * 2][1] = rh[2]; bh[np * 2 + 1][1] = rh[3];
            bl[np * 2][0] = rl[0]; bl[np * 2 + 1][0] = rl[1];
            bl[np * 2][1] = rl[2]; bl[np * 2 + 1][1] = rl[3];
        }
#pragma unroll
        for (int mf = 0; mf < 2; ++mf)
#pragma unroll
            for (int nf = 0; nf < 4; ++nf)
                mma_bf16(acc[mf][nf], ah[mf], bh[nf]);
#pragma unroll
        for (int mf = 0; mf < 2; ++mf)
#pragma unroll
            for (int nf = 0; nf < 4; ++nf)
                mma_bf16(acc[mf][nf], al[mf], bh[nf]);
#pragma unroll
        for (int mf = 0; mf < 2; ++mf)
#pragma unroll
            for (int nf = 0; nf < 4; ++nf)
                mma_bf16(acc[mf][nf], ah[mf], bl[nf]);
    }

    const float inv_sqrt_emb = 0.04419417382415922f;
#pragma unroll
    for (int mf = 0; mf < 2; ++mf) {
#pragma unroll
        for (int nf = 0; nf < 4; ++nf) {
#pragma unroll
            for (int t = 0; t < 4; ++t) {
                const int r = bm + wm * 32 + mf * 16 + g + ((t >> 1) << 3);
                const int c = bn + wn * 32 + nf * 8 + 2 * tig + (t & 1);
                if (r < POMO && c < PROB) {
                    const size_t off = ((size_t)b * POMO + r) * PROB + c;
                    out[off] = 10.f * tanhf(acc[mf][nf][t] * inv_sqrt_emb) + mask[off];
                }
            }
        }
    }
}

// ---------------------------------------------------------------------------
// In-place row softmax over 200 columns, one warp per row.
// ---------------------------------------------------------------------------
__global__ __launch_bounds__(256) void softmax_kernel(float* __restrict__ out)
{
    const int row  = blockIdx.x * 8 + (threadIdx.x >> 5);
    const int lane = threadIdx.x & 31;
    float* p = out + (size_t)row * PROB;

    float v[7];
    float mx = -1e30f;
#pragma unroll
    for (int i = 0; i < 7; ++i) {
        int c = lane + (i << 5);
        v[i] = (c < PROB) ? p[c] : -1e30f;
        mx = fmaxf(mx, v[i]);
    }
#pragma unroll
    for (int off = 16; off; off >>= 1)
        mx = fmaxf(mx, __shfl_xor_sync(0xffffffffu, mx, off));

    float sum = 0.f;
#pragma unroll
    for (int i = 0; i < 7; ++i) { v[i] = __expf(v[i] - mx); sum += v[i]; }
#pragma unroll
    for (int off = 16; off; off >>= 1)
        sum += __shfl_xor_sync(0xffffffffu, sum, off);

    float inv = 1.f / sum;
#pragma unroll
    for (int i = 0; i < 7; ++i) {
        int c = lane + (i << 5);
        if (c < PROB) p[c] = v[i] * inv;
    }
}

// ---------------------------------------------------------------------------
// Launch
// ---------------------------------------------------------------------------
extern "C" void kernel_launch(void* const* d_in, const int* in_sizes, int n_in,
                              void* d_out, int out_size)
{
    const float* nodes = (const float*)d_in[0];
    const float* q1    = (const float*)d_in[1];
    const float* lastn = (const float*)d_in[2];
    const float* mask  = (const float*)d_in[3];
    const float* Wqf   = (const float*)d_in[4];
    const float* Wql   = (const float*)d_in[5];
    const float* Wk    = (const float*)d_in[6];
    const float* Wv    = (const float*)d_in[7];
    const float* Wc    = (const float*)d_in[8];
    const float* bc    = (const float*)d_in[9];
    float* out = (float*)d_out;

    __nv_bfloat16 *nh, *nl, *q1h, *q1l, *lnh, *lnl, *Oh, *Ol, *MHh, *MHl;
    __nv_bfloat16 *Khb, *Klb, *Vhb, *Vlb, *Qhb, *Qlb;
    __nv_bfloat16 *Wkh, *Wkl, *Wvh, *Wvl, *Wqfh, *Wqfl, *Wqlh, *Wqll, *Wch, *Wcl;
    cudaGetSymbolAddress((void**)&nh,   g_nh);   cudaGetSymbolAddress((void**)&nl,   g_nl);
    cudaGetSymbolAddress((void**)&q1h,  g_q1h);  cudaGetSymbolAddress((void**)&q1l,  g_q1l);
    cudaGetSymbolAddress((void**)&lnh,  g_lnh);  cudaGetSymbolAddress((void**)&lnl,  g_lnl);
    cudaGetSymbolAddress((void**)&Oh,   g_Oh);   cudaGetSymbolAddress((void**)&Ol,   g_Ol);
    cudaGetSymbolAddress((void**)&MHh,  g_MHh);  cudaGetSymbolAddress((void**)&MHl,  g_MHl);
    cudaGetSymbolAddress((void**)&Khb,  g_Kh);   cudaGetSymbolAddress((void**)&Klb,  g_Kl);
    cudaGetSymbolAddress((void**)&Vhb,  g_Vh);   cudaGetSymbolAddress((void**)&Vlb,  g_Vl);
    cudaGetSymbolAddress((void**)&Qhb,  g_Qh);   cudaGetSymbolAddress((void**)&Qlb,  g_Ql);
    cudaGetSymbolAddress((void**)&Wkh,  g_Wkh);  cudaGetSymbolAddress((void**)&Wkl,  g_Wkl);
    cudaGetSymbolAddress((void**)&Wvh,  g_Wvh);  cudaGetSymbolAddress((void**)&Wvl,  g_Wvl);
    cudaGetSymbolAddress((void**)&Wqfh, g_Wqfh); cudaGetSymbolAddress((void**)&Wqfl, g_Wqfl);
    cudaGetSymbolAddress((void**)&Wqlh, g_Wqlh); cudaGetSymbolAddress((void**)&Wqll, g_Wqll);
    cudaGetSymbolAddress((void**)&Wch,  g_Wch);  cudaGetSymbolAddress((void**)&Wcl,  g_Wcl);

    const int gemm_smem = 4 * GST * ATI * 4;                       // 73728
    cudaFuncSetAttribute(gemm_bf16x3,
                         cudaFuncAttributeMaxDynamicSharedMemorySize, gemm_smem);
    cudaFuncSetAttribute(gemm_kv,
                         cudaFuncAttributeMaxDynamicSharedMemorySize, gemm_smem);
    const int s2_smem = (2 * GST * S_ATI + 2 * GST * S_BTI) * 4;   // 55296
    cudaFuncSetAttribute(score2_bf16,
                         cudaFuncAttributeMaxDynamicSharedMemorySize, s2_smem);
    cudaFuncSetAttribute(attn_mma,
                         cudaFuncAttributeMaxDynamicSharedMemorySize, ATTN_SMEM);

    // --- split-convert inputs (2 launches) ---
    const int nNodes = BB * NNODE * EMB, nAct = BB * POMO * EMB;
    {
        dim3 gc((nNodes / 4 + 255) / 256, 1, 3);
        convsplit3<<<gc, 256>>>(nodes, nh, nl, nNodes,
                                q1, q1h, q1l, nAct,
                                lastn, lnh, lnl, nAct);
        dim3 tg(16, 16, 5), tb(32, 8);
        transconv5<<<tg, tb>>>(Wk,  Wkh,  Wkl,  Wv,  Wvh,  Wvl,
                               Wqf, Wqfh, Wqfl, Wql, Wqlh, Wqll,
                               Wc,  Wch,  Wcl);
    }

    // --- fused K+V projection ---
    dim3 gKVm(2 * EMB / 128, (BB * NNODE + 127) / 128);  // 8 x 101
    gemm_kv<<<gKVm, 256, gemm_smem>>>(nh, nl, Wkh, Wkl, Wvh, Wvl,
                                      Khb, Klb, Vhb, Vlb, BB * NNODE);

    // --- Q projection (dual A) ---
    dim3 gQ(EMB / 128, (BB * POMO) / 128);               // 4 x 100
    gemm_bf16x3<<<gQ, 256, gemm_smem>>>(q1h, q1l, Wqfh, Wqfl,
        lnh, lnl, Wqlh, Wqll, nullptr, nullptr, Qhb, Qlb,
        BB * POMO, EMB, EMB);

    // --- tensor-core flash attention ---
    attn_mma<<<dim3(4, NH, BB), 128, ATTN_SMEM>>>(Qhb, Qlb, Khb, Klb,
                                                  Vhb, Vlb, mask, Oh, Ol);

    // --- Wc projection (emit bf16 split for score2) ---
    gemm_bf16x3<<<gQ, 256, gemm_smem>>>(Oh, Ol, Wch, Wcl,
        nullptr, nullptr, nullptr, nullptr, bc, nullptr, MHh, MHl,
        BB * POMO, EMB, EMB);

    // --- score2 + softmax ---
    dim3 gS(2, 4, BB);
    score2_bf16<<<gS, 256, s2_smem>>>(MHh, MHl, nh, nl, mask, out);

    softmax_kernel<<<(BB * POMO) / 8, 256>>>(out);
}